// round 5
// baseline (speedup 1.0000x reference)
#include <cuda_runtime.h>
#include <math.h>

// Shapes (fixed by the problem)
#define H    768
#define T    512
#define NC   8
#define NCT  4096
#define NL   8921
#define NN   4
#define RSPLIT 1115      // lw rows 1115*c (c=1..7) are split across chunks c-1/c

// Partition config
#define NSUB     32      // 512 rows per chunk -> 32 sub-blocks of 16 rows
#define SUBROWS  16
#define SLICELEN 24
#define NSLICE   372     // ceil(8921/24)
#define H4       192     // H / 4

#define NB_ENC (NC * NSUB)        // 256 encoding blocks
#define NB_LW  NSLICE             // 372 lw blocks
#define NBLK   (NB_ENC + NB_LW)   // 628 total

__device__ float g_B[8 * H];        // per-chunk enc column sums (atomic accum)
__device__ float g_L[8 * H];        // per-chunk lw row sums     (atomic accum)
__device__ unsigned g_ticket = 0;   // last-block election; self-resetting

// note_end_chunk_ids may be int32 or int64 on device; detect from word pattern.
__device__ __forceinline__ void load_ids(const int* __restrict__ w, int ids[4]) {
    int a0 = w[0], a1 = w[1], a2 = w[2], a3 = w[3];
    bool maybe64 = (a1 == 0 && a3 == 0 && a0 >= 0 && a0 < NC && a2 >= a0 && a2 < NC);
    if (maybe64) {
        int b2 = w[4], b2h = w[5], b3 = w[6], b3h = w[7];
        if (b2h == 0 && b3h == 0 && b2 >= a2 && b2 < NC && b3 >= b2 && b3 < NC) {
            ids[0] = a0; ids[1] = a2; ids[2] = b2; ids[3] = b3;
            return;
        }
    }
    ids[0] = a0; ids[1] = a1; ids[2] = a2; ids[3] = a3;
}

__device__ __forceinline__ void acc4(float4& s, const float4 v) {
    s.x += v.x; s.y += v.y; s.z += v.z; s.w += v.w;
}

__device__ __forceinline__ void red4(float* dst, int k4, const float4 v) {
    atomicAdd(dst + k4 * 4 + 0, v.x);
    atomicAdd(dst + k4 * 4 + 1, v.y);
    atomicAdd(dst + k4 * 4 + 2, v.z);
    atomicAdd(dst + k4 * 4 + 3, v.w);
}

// Single fused kernel: streaming block-sums (REDG accumulate) + last-block
// final combine (softmax-collapse closed form + sigmoid).
__global__ void __launch_bounds__(192, 8)
k_main(const float* __restrict__ enc, const float* __restrict__ lw,
       const int* __restrict__ idw, float* __restrict__ out) {
    int b = blockIdx.x;
    int t = threadIdx.x;           // k4 lane, 0..191
    if (b < NB_ENC) {
        int chunk = b >> 5, sub = b & 31;
        const float4* p = (const float4*)enc + (size_t)(chunk * T + sub * SUBROWS) * H4 + t;
        float4 a[8];
        #pragma unroll
        for (int i = 0; i < 8; ++i) a[i] = make_float4(0.f, 0.f, 0.f, 0.f);
        #pragma unroll
        for (int r = 0; r < SUBROWS; ++r) acc4(a[r & 7], p[(size_t)r * H4]);
        #pragma unroll
        for (int i = 0; i < 4; ++i) acc4(a[i], a[i + 4]);
        acc4(a[0], a[2]); acc4(a[1], a[3]); acc4(a[0], a[1]);
        red4(g_B + chunk * H, t, a[0]);
    } else {
        int is = b - NB_ENC;
        int i0 = is * SLICELEN;
        int i1 = min(i0 + SLICELEN, NL);
        int i = i0;
        while (i < i1) {
            int c   = i / RSPLIT;
            int rem = i - c * RSPLIT;
            if (rem == 0 && c >= 1 && c <= 7) { ++i; continue; }  // split row: handled below
            int ch = (c > 7) ? 7 : c;                             // row 8920 -> chunk 7
            int segend = min(i1, (c + 1) * RSPLIT);
            const float4* p = (const float4*)lw + (size_t)i * H4 + t;
            int n = segend - i;
            float4 a[4];
            #pragma unroll
            for (int j = 0; j < 4; ++j) a[j] = make_float4(0.f, 0.f, 0.f, 0.f);
            #pragma unroll 8
            for (int r = 0; r < n; ++r) acc4(a[r & 3], p[(size_t)r * H4]);
            acc4(a[0], a[2]); acc4(a[1], a[3]); acc4(a[0], a[1]);
            red4(g_L + ch * H, t, a[0]);
            i = segend;
        }
    }

    // ── Last-block election ──────────────────────────────────────────────
    __threadfence();                       // make this block's REDGs visible
    __shared__ int s_last;
    if (t == 0) {
        unsigned old = atomicAdd(&g_ticket, 1u);
        s_last = (old == NBLK - 1u);
        if (s_last) atomicExch(&g_ticket, 0u);   // reset for graph replay
    }
    __syncthreads();
    if (!s_last) return;

    // ── Final combine (one block, 192 threads x 4 k-values) ─────────────
    int ids[4];
    load_ids(idw, ids);
    float v[4][8];
    #pragma unroll
    for (int c = 0; c < 8; ++c) {
        int cnt = 0;
        #pragma unroll
        for (int n = 0; n < 4; ++n) cnt += (ids[n] < c);
        float inv = (cnt > 0) ? 1.f / (float)cnt : 0.f;
        #pragma unroll
        for (int n = 0; n < 4; ++n)
            v[n][c] = (cnt == 0) ? 0.25f : ((ids[n] < c) ? inv : 0.f);
    }

    #pragma unroll
    for (int kk = 0; kk < 4; ++kk) {
        int k = kk * 192 + t;

        float B[8], L[8];
        #pragma unroll
        for (int c = 0; c < 8; ++c) {
            B[c] = __ldcg(&g_B[c * H + k]);   // L2 loads: see all SMs' REDGs
            L[c] = __ldcg(&g_L[c * H + k]);
        }

        float P[9];
        P[0] = 0.f;
        #pragma unroll
        for (int c = 0; c < 8; ++c) P[c + 1] = P[c] + B[c];
        float E = P[8];

        // S_c[k] = L_c*E + split-row boundary terms
        float S[8];
        #pragma unroll
        for (int c = 0; c < 8; ++c) {
            float s = L[c] * E;
            if (c >= 1) s += lw[(size_t)(RSPLIT * c) * H + k] * (E - P[c]);
            if (c <= 6) s += lw[(size_t)(RSPLIT * (c + 1)) * H + k] * P[c + 1];
            S[c] = s;
        }

        #pragma unroll
        for (int n = 0; n < 4; ++n) {
            float sc = 0.f;
            #pragma unroll
            for (int c = 0; c < 8; ++c) sc += v[n][c] * S[c];
            out[n * H + k] = 1.f / (1.f + expf(-sc));
        }
    }
}

extern "C" void kernel_launch(void* const* d_in, const int* in_sizes, int n_in,
                              void* d_out, int out_size) {
    // Locate inputs by element count; fall back to declared order.
    int ie = 0, ilw = 2, iid = 3;
    int hnl_seen = 0;
    for (int i = 0; i < n_in; ++i) {
        long long sz = in_sizes[i];
        if (sz == (long long)NCT * H) ie = i;
        else if (sz == (long long)H * NL) { if (hnl_seen++) ilw = i; }
        else if (sz == NN) iid = i;
    }
    const float* enc = (const float*)d_in[ie];
    const float* lw  = (const float*)d_in[ilw];
    const int*   idw = (const int*)d_in[iid];

    void* pB = nullptr; void* pL = nullptr;
    cudaGetSymbolAddress(&pB, g_B);
    cudaGetSymbolAddress(&pL, g_L);
    cudaMemsetAsync(pB, 0, 8 * H * sizeof(float));
    cudaMemsetAsync(pL, 0, 8 * H * sizeof(float));

    k_main<<<NBLK, 192>>>(enc, lw, idw, (float*)d_out);
}

// round 7
// speedup vs baseline: 1.7541x; 1.7541x over previous
#include <cuda_runtime.h>
#include <math.h>

// Shapes (fixed by the problem)
#define H    768
#define T    512
#define NC   8
#define NCT  4096
#define NL   8921
#define NN   4
#define RSPLIT 1115      // lw rows 1115*c (c=1..7) are split across chunks c-1/c

// Partition config
#define NSUB     32      // 512 rows per chunk -> 32 sub-blocks of 16 rows
#define SUBROWS  16
#define SLICELEN 24
#define NSLICE   372     // ceil(8921/24)
#define H4       192     // H / 4

#define NB_ENC (NC * NSUB)        // 256 encoding blocks
#define NB_LW  NSLICE             // 372 lw blocks
#define NBLK   (NB_ENC + NB_LW)

// Single combined accumulator: [0,8H) = per-chunk enc col sums (B),
// [8H,16H) = per-chunk lw row sums (L). One memset node.
__device__ float g_acc[16 * H];

// note_end_chunk_ids may be int32 or int64 on device; detect from word pattern.
__device__ __forceinline__ void load_ids(const int* __restrict__ w, int ids[4]) {
    int a0 = w[0], a1 = w[1], a2 = w[2], a3 = w[3];
    bool maybe64 = (a1 == 0 && a3 == 0 && a0 >= 0 && a0 < NC && a2 >= a0 && a2 < NC);
    if (maybe64) {
        int b2 = w[4], b2h = w[5], b3 = w[6], b3h = w[7];
        if (b2h == 0 && b3h == 0 && b2 >= a2 && b2 < NC && b3 >= b2 && b3 < NC) {
            ids[0] = a0; ids[1] = a2; ids[2] = b2; ids[3] = b3;
            return;
        }
    }
    ids[0] = a0; ids[1] = a1; ids[2] = a2; ids[3] = a3;
}

__device__ __forceinline__ void acc4(float4& s, const float4 v) {
    s.x += v.x; s.y += v.y; s.z += v.z; s.w += v.w;
}

__device__ __forceinline__ float4 ldcs4(const float4* p) {
    return __ldcs(p);   // streaming load, evict-first: data is touched once
}

__device__ __forceinline__ void red4(float* dst, int k4, const float4 v) {
    atomicAdd(dst + k4 * 4 + 0, v.x);
    atomicAdd(dst + k4 * 4 + 1, v.y);
    atomicAdd(dst + k4 * 4 + 2, v.z);
    atomicAdd(dst + k4 * 4 + 3, v.w);
}

// Streaming pass: float4, one full 768-col row per 192-thread block.
// No min-blocks clause: let ptxas use ~90 regs so all 16 row-loads can be
// in flight (MLP ~16) instead of the 40-reg / MLP~6 version.
__global__ void __launch_bounds__(192)
k_main(const float* __restrict__ enc, const float* __restrict__ lw) {
    int b = blockIdx.x;
    int t = threadIdx.x;           // k4 lane, 0..191
    if (b < NB_ENC) {
        int chunk = b >> 5, sub = b & 31;
        const float4* p = (const float4*)enc + (size_t)(chunk * T + sub * SUBROWS) * H4 + t;
        float4 v[SUBROWS];
        #pragma unroll
        for (int r = 0; r < SUBROWS; ++r) v[r] = ldcs4(p + (size_t)r * H4);
        // tree reduce 16 -> 1
        #pragma unroll
        for (int s = 8; s >= 1; s >>= 1)
            #pragma unroll
            for (int i = 0; i < s; ++i) acc4(v[i], v[i + s]);
        red4(g_acc + chunk * H, t, v[0]);
    } else {
        int is = b - NB_ENC;
        int i0 = is * SLICELEN;
        int i1 = min(i0 + SLICELEN, NL);
        int i = i0;
        while (i < i1) {
            int c   = i / RSPLIT;
            int rem = i - c * RSPLIT;
            if (rem == 0 && c >= 1 && c <= 7) { ++i; continue; }  // split row: handled in k_final
            int ch = (c > 7) ? 7 : c;                             // row 8920 -> chunk 7
            int segend = min(i1, (c + 1) * RSPLIT);
            const float4* p = (const float4*)lw + (size_t)i * H4 + t;
            int n = segend - i;
            float4 a[8];
            #pragma unroll
            for (int j = 0; j < 8; ++j) a[j] = make_float4(0.f, 0.f, 0.f, 0.f);
            int r = 0;
            for (; r + 8 <= n; r += 8) {
                float4 v0 = ldcs4(p + (size_t)(r + 0) * H4);
                float4 v1 = ldcs4(p + (size_t)(r + 1) * H4);
                float4 v2 = ldcs4(p + (size_t)(r + 2) * H4);
                float4 v3 = ldcs4(p + (size_t)(r + 3) * H4);
                float4 v4 = ldcs4(p + (size_t)(r + 4) * H4);
                float4 v5 = ldcs4(p + (size_t)(r + 5) * H4);
                float4 v6 = ldcs4(p + (size_t)(r + 6) * H4);
                float4 v7 = ldcs4(p + (size_t)(r + 7) * H4);
                acc4(a[0], v0); acc4(a[1], v1); acc4(a[2], v2); acc4(a[3], v3);
                acc4(a[4], v4); acc4(a[5], v5); acc4(a[6], v6); acc4(a[7], v7);
            }
            for (; r < n; ++r) acc4(a[r & 7], ldcs4(p + (size_t)r * H4));
            #pragma unroll
            for (int j = 0; j < 4; ++j) acc4(a[j], a[j + 4]);
            acc4(a[0], a[2]); acc4(a[1], a[3]); acc4(a[0], a[1]);
            red4(g_acc + (8 + ch) * H, t, a[0]);
            i = segend;
        }
    }
}

// Final combine: tiny (768 lanes of k), ~30 loads per thread.
__global__ void __launch_bounds__(128)
k_final(const float* __restrict__ lw, const int* __restrict__ idw,
        float* __restrict__ out) {
    int k = blockIdx.x * 128 + threadIdx.x;   // grid = 6

    int ids[4];
    load_ids(idw, ids);
    float v[4][8];
    #pragma unroll
    for (int c = 0; c < 8; ++c) {
        int cnt = 0;
        #pragma unroll
        for (int n = 0; n < 4; ++n) cnt += (ids[n] < c);
        float inv = (cnt > 0) ? 1.f / (float)cnt : 0.f;
        #pragma unroll
        for (int n = 0; n < 4; ++n)
            v[n][c] = (cnt == 0) ? 0.25f : ((ids[n] < c) ? inv : 0.f);
    }

    float B[8], L[8];
    #pragma unroll
    for (int c = 0; c < 8; ++c) {
        B[c] = g_acc[c * H + k];
        L[c] = g_acc[(8 + c) * H + k];
    }

    float P[9];
    P[0] = 0.f;
    #pragma unroll
    for (int c = 0; c < 8; ++c) P[c + 1] = P[c] + B[c];
    float E = P[8];

    // S_c[k] = L_c*E + split-row boundary terms
    float S[8];
    #pragma unroll
    for (int c = 0; c < 8; ++c) {
        float s = L[c] * E;
        if (c >= 1) s += lw[(size_t)(RSPLIT * c) * H + k] * (E - P[c]);
        if (c <= 6) s += lw[(size_t)(RSPLIT * (c + 1)) * H + k] * P[c + 1];
        S[c] = s;
    }

    #pragma unroll
    for (int n = 0; n < 4; ++n) {
        float sc = 0.f;
        #pragma unroll
        for (int c = 0; c < 8; ++c) sc += v[n][c] * S[c];
        out[n * H + k] = 1.f / (1.f + expf(-sc));
    }
}

extern "C" void kernel_launch(void* const* d_in, const int* in_sizes, int n_in,
                              void* d_out, int out_size) {
    // Locate inputs by element count; fall back to declared order.
    int ie = 0, ilw = 2, iid = 3;
    int hnl_seen = 0;
    for (int i = 0; i < n_in; ++i) {
        long long sz = in_sizes[i];
        if (sz == (long long)NCT * H) ie = i;
        else if (sz == (long long)H * NL) { if (hnl_seen++) ilw = i; }
        else if (sz == NN) iid = i;
    }
    const float* enc = (const float*)d_in[ie];
    const float* lw  = (const float*)d_in[ilw];
    const int*   idw = (const int*)d_in[iid];

    void* pA = nullptr;
    cudaGetSymbolAddress(&pA, g_acc);
    cudaMemsetAsync(pA, 0, 16 * H * sizeof(float));

    k_main<<<NBLK, 192>>>(enc, lw);
    k_final<<<6, 128>>>(lw, idw, (float*)d_out);
}

// round 10
// speedup vs baseline: 1.8136x; 1.0339x over previous
#include <cuda_runtime.h>
#include <math.h>

// Shapes (fixed by the problem)
#define H    768
#define T    512
#define NC   8
#define NCT  4096
#define NL   8921
#define NN   4
#define RSPLIT 1115      // lw rows 1115*c (c=1..7) are split across chunks c-1/c

// Partition config
#define NSUB     32      // 512 rows per chunk -> 32 sub-blocks of 16 rows
#define SUBROWS  16
#define SLICELEN 24
#define NSLICE   372     // ceil(8921/24)
#define H4       192     // H / 4

#define NB_ENC (NC * NSUB)        // 256 encoding blocks
#define NB_LW  NSLICE             // 372 lw blocks
#define NBLK   (NB_ENC + NB_LW)

// Combined accumulator: [0,8H) = per-chunk enc col sums (B),
// [8H,16H) = per-chunk lw row sums (L). Zero-initialized at load;
// k_final re-zeros after reading -> self-cleaning across graph replays.
__device__ float g_acc[16 * H];

// note_end_chunk_ids may be int32 or int64 on device; detect from word pattern.
__device__ __forceinline__ void load_ids(const int* __restrict__ w, int ids[4]) {
    int a0 = w[0], a1 = w[1], a2 = w[2], a3 = w[3];
    bool maybe64 = (a1 == 0 && a3 == 0 && a0 >= 0 && a0 < NC && a2 >= a0 && a2 < NC);
    if (maybe64) {
        int b2 = w[4], b2h = w[5], b3 = w[6], b3h = w[7];
        if (b2h == 0 && b3h == 0 && b2 >= a2 && b2 < NC && b3 >= b2 && b3 < NC) {
            ids[0] = a0; ids[1] = a2; ids[2] = b2; ids[3] = b3;
            return;
        }
    }
    ids[0] = a0; ids[1] = a1; ids[2] = a2; ids[3] = a3;
}

__device__ __forceinline__ void acc4(float4& s, const float4 v) {
    s.x += v.x; s.y += v.y; s.z += v.z; s.w += v.w;
}

__device__ __forceinline__ float4 ldcs4(const float4* p) {
    return __ldcs(p);   // streaming load, evict-first: data is touched once
}

__device__ __forceinline__ void red4(float* dst, int k4, const float4 v) {
    atomicAdd(dst + k4 * 4 + 0, v.x);
    atomicAdd(dst + k4 * 4 + 1, v.y);
    atomicAdd(dst + k4 * 4 + 2, v.z);
    atomicAdd(dst + k4 * 4 + 3, v.w);
}

// Streaming pass: float4, one full 768-col row per 192-thread block.
// No min-blocks clause: ~90 regs so all 16 row-loads are in flight (MLP ~16).
__global__ void __launch_bounds__(192)
k_main(const float* __restrict__ enc, const float* __restrict__ lw) {
    int b = blockIdx.x;
    int t = threadIdx.x;           // k4 lane, 0..191
    if (b < NB_ENC) {
        int chunk = b >> 5, sub = b & 31;
        const float4* p = (const float4*)enc + (size_t)(chunk * T + sub * SUBROWS) * H4 + t;
        float4 v[SUBROWS];
        #pragma unroll
        for (int r = 0; r < SUBROWS; ++r) v[r] = ldcs4(p + (size_t)r * H4);
        #pragma unroll
        for (int s = 8; s >= 1; s >>= 1)
            #pragma unroll
            for (int i = 0; i < s; ++i) acc4(v[i], v[i + s]);
        red4(g_acc + chunk * H, t, v[0]);
    } else {
        int is = b - NB_ENC;
        int i0 = is * SLICELEN;
        int i1 = min(i0 + SLICELEN, NL);
        int i = i0;
        while (i < i1) {
            int c   = i / RSPLIT;
            int rem = i - c * RSPLIT;
            if (rem == 0 && c >= 1 && c <= 7) { ++i; continue; }  // split row: handled in k_final
            int ch = (c > 7) ? 7 : c;                             // row 8920 -> chunk 7
            int segend = min(i1, (c + 1) * RSPLIT);
            const float4* p = (const float4*)lw + (size_t)i * H4 + t;
            int n = segend - i;
            float4 a[8];
            #pragma unroll
            for (int j = 0; j < 8; ++j) a[j] = make_float4(0.f, 0.f, 0.f, 0.f);
            int r = 0;
            for (; r + 8 <= n; r += 8) {
                float4 v0 = ldcs4(p + (size_t)(r + 0) * H4);
                float4 v1 = ldcs4(p + (size_t)(r + 1) * H4);
                float4 v2 = ldcs4(p + (size_t)(r + 2) * H4);
                float4 v3 = ldcs4(p + (size_t)(r + 3) * H4);
                float4 v4 = ldcs4(p + (size_t)(r + 4) * H4);
                float4 v5 = ldcs4(p + (size_t)(r + 5) * H4);
                float4 v6 = ldcs4(p + (size_t)(r + 6) * H4);
                float4 v7 = ldcs4(p + (size_t)(r + 7) * H4);
                acc4(a[0], v0); acc4(a[1], v1); acc4(a[2], v2); acc4(a[3], v3);
                acc4(a[4], v4); acc4(a[5], v5); acc4(a[6], v6); acc4(a[7], v7);
            }
            for (; r < n; ++r) acc4(a[r & 7], ldcs4(p + (size_t)r * H4));
            #pragma unroll
            for (int j = 0; j < 4; ++j) acc4(a[j], a[j + 4]);
            acc4(a[0], a[2]); acc4(a[1], a[3]); acc4(a[0], a[1]);
            red4(g_acc + (8 + ch) * H, t, a[0]);
            i = segend;
        }
    }
}

// Final combine, PDL-overlapped: all k_main-independent loads happen BEFORE
// cudaGridDependencySynchronize(); only g_acc reads after. Re-zeros g_acc.
__global__ void __launch_bounds__(768)
k_final(const float* __restrict__ lw, const int* __restrict__ idw,
        float* __restrict__ out) {
    int k = threadIdx.x;    // grid = 1, 768 threads

    // ── Pre-sync phase (independent of k_main) ──────────────────────────
    int ids[4];
    load_ids(idw, ids);
    float v[4][8];
    #pragma unroll
    for (int c = 0; c < 8; ++c) {
        int cnt = 0;
        #pragma unroll
        for (int n = 0; n < 4; ++n) cnt += (ids[n] < c);
        float inv = (cnt > 0) ? 1.f / (float)cnt : 0.f;
        #pragma unroll
        for (int n = 0; n < 4; ++n)
            v[n][c] = (cnt == 0) ? 0.25f : ((ids[n] < c) ? inv : 0.f);
    }
    float lwr[8];   // lw[RSPLIT*c][k] for c=1..7
    #pragma unroll
    for (int c = 1; c <= 7; ++c)
        lwr[c] = __ldg(&lw[(size_t)(RSPLIT * c) * H + k]);

    // ── Wait for k_main (launch-dependency machinery; completes with
    //    stream-order memory visibility, no threadfence anywhere) ────────
    cudaGridDependencySynchronize();

    float B[8], L[8];
    #pragma unroll
    for (int c = 0; c < 8; ++c) {
        B[c] = g_acc[c * H + k];
        L[c] = g_acc[(8 + c) * H + k];
    }
    // Self-clean for the next graph replay.
    #pragma unroll
    for (int c = 0; c < 16; ++c) g_acc[c * H + k] = 0.f;

    float P[9];
    P[0] = 0.f;
    #pragma unroll
    for (int c = 0; c < 8; ++c) P[c + 1] = P[c] + B[c];
    float E = P[8];

    // S_c[k] = L_c*E + split-row boundary terms
    float S[8];
    #pragma unroll
    for (int c = 0; c < 8; ++c) {
        float s = L[c] * E;
        if (c >= 1) s += lwr[c] * (E - P[c]);
        if (c <= 6) s += lwr[c + 1] * P[c + 1];
        S[c] = s;
    }

    #pragma unroll
    for (int n = 0; n < 4; ++n) {
        float sc = 0.f;
        #pragma unroll
        for (int c = 0; c < 8; ++c) sc += v[n][c] * S[c];
        out[n * H + k] = 1.f / (1.f + expf(-sc));
    }
}

extern "C" void kernel_launch(void* const* d_in, const int* in_sizes, int n_in,
                              void* d_out, int out_size) {
    // Locate inputs by element count; fall back to declared order.
    int ie = 0, ilw = 2, iid = 3;
    int hnl_seen = 0;
    for (int i = 0; i < n_in; ++i) {
        long long sz = in_sizes[i];
        if (sz == (long long)NCT * H) ie = i;
        else if (sz == (long long)H * NL) { if (hnl_seen++) ilw = i; }
        else if (sz == NN) iid = i;
    }
    const float* enc = (const float*)d_in[ie];
    const float* lw  = (const float*)d_in[ilw];
    const int*   idw = (const int*)d_in[iid];

    k_main<<<NBLK, 192>>>(enc, lw);

    // PDL launch: k_final spins up while k_main drains. If the launch-ex
    // path errors for any reason, fall back to a plain serialized launch
    // (correctness never depends on PDL firing).
    cudaLaunchAttribute attr[1] = {};
    attr[0].id = cudaLaunchAttributeProgrammaticStreamSerialization;
    attr[0].val.programmaticStreamSerializationAllowed = 1;

    cudaLaunchConfig_t cfg = {};
    cfg.gridDim  = dim3(1, 1, 1);
    cfg.blockDim = dim3(768, 1, 1);
    cfg.dynamicSmemBytes = 0;
    cfg.stream = (cudaStream_t)0;
    cfg.attrs = attr;
    cfg.numAttrs = 1;

    cudaError_t e = cudaLaunchKernelEx(&cfg, k_final, lw, idw, (float*)d_out);
    if (e != cudaSuccess) {
        (void)cudaGetLastError();   // clear sticky error before fallback
        k_final<<<1, 768>>>(lw, idw, (float*)d_out);
    }
}